// round 10
// baseline (speedup 1.0000x reference)
#include <cuda_runtime.h>
#include <cuda_bf16.h>

#define BATCH 2
#define NSEQ 1024
#define DIM 256
#define PDIM 64
#define MAXREL 32
#define NEMBED (2 * MAXREL + 1)
#define NROWS (BATCH * NSEQ)
#define IT 4    // i-rows per block in pair_kernel
#define PR 8    // rows per block in proj_kernel

// Scratch
__device__ float g_proj_i[NROWS * PDIM];
__device__ float g_proj_j[NROWS * PDIM];
__device__ float g_proj_jT[BATCH * PDIM * NSEQ];   // [b][p][j] transposed copy
__device__ __align__(16) float2 g_mt_i[NROWS];     // {mean, mean-of-squares}
__device__ __align__(16) float2 g_mt_j[NROWS];

// ---------------------------------------------------------------------------
// Kernel 1: projections, 8 rows per block.
// 256 threads = 128 cols (64 for proj_i, 64 for proj_j) x 2 row-groups of 4.
// W loads amortized over 4 rows; smem row reads are warp-broadcast LDS.128.
// ---------------------------------------------------------------------------
__global__ __launch_bounds__(256) void proj_kernel(
    const float* __restrict__ single, const float* __restrict__ W,
    const float* __restrict__ bias)
{
    __shared__ __align__(16) float s[PR][DIM];     // 8 KB
    const int rb = blockIdx.x * PR;
    const int t = threadIdx.x;

    // stage 8 rows of single (512 float4, 2 per thread, coalesced)
    {
        const float4* src = (const float4*)(single + (size_t)rb * DIM);
        float4* s4 = (float4*)s;
        s4[t]       = src[t];
        s4[t + 256] = src[t + 256];
    }
    __syncthreads();

    const int c   = t & 127;          // output column 0..127
    const int g   = t >> 7;           // row group (0/1) -> rows g*4..g*4+3
    const int p   = c & 63;
    const bool isj = (c >= 64);
    const float* __restrict__ Wc = W + (isj ? DIM * PDIM : 0) + p;

    float acc0 = 0.f, acc1 = 0.f, acc2 = 0.f, acc3 = 0.f;
#pragma unroll 4
    for (int d = 0; d < DIM; d += 4) {
        const float w0 = Wc[(d + 0) * PDIM];
        const float w1 = Wc[(d + 1) * PDIM];
        const float w2 = Wc[(d + 2) * PDIM];
        const float w3 = Wc[(d + 3) * PDIM];
        const float4 s0 = *(const float4*)&s[g * 4 + 0][d];
        const float4 s1 = *(const float4*)&s[g * 4 + 1][d];
        const float4 s2 = *(const float4*)&s[g * 4 + 2][d];
        const float4 s3 = *(const float4*)&s[g * 4 + 3][d];
        acc0 = fmaf(s0.x, w0, fmaf(s0.y, w1, fmaf(s0.z, w2, fmaf(s0.w, w3, acc0))));
        acc1 = fmaf(s1.x, w0, fmaf(s1.y, w1, fmaf(s1.z, w2, fmaf(s1.w, w3, acc1))));
        acc2 = fmaf(s2.x, w0, fmaf(s2.y, w1, fmaf(s2.z, w2, fmaf(s2.w, w3, acc2))));
        acc3 = fmaf(s3.x, w0, fmaf(s3.y, w1, fmaf(s3.z, w2, fmaf(s3.w, w3, acc3))));
    }

    const float badd = isj ? bias[p] : 0.f;
    float accs[4] = {acc0, acc1, acc2, acc3};
#pragma unroll
    for (int r = 0; r < 4; r++) {
        const int row = rb + g * 4 + r;
        const float v = accs[r] + badd;
        if (!isj) {
            g_proj_i[(size_t)row * PDIM + p] = v;
        } else {
            g_proj_j[(size_t)row * PDIM + p] = v;
            const int b = row >> 10, n = row & (NSEQ - 1);
            g_proj_jT[((size_t)b * PDIM + p) * NSEQ + n] = v;
        }
    }
}

// ---------------------------------------------------------------------------
// Kernel 2 (tiny): per-row {mean, mean-of-squares} for both projections.
// ---------------------------------------------------------------------------
__global__ __launch_bounds__(256) void stats_kernel()
{
    const int gw = (blockIdx.x * 256 + threadIdx.x) >> 5;
    const int lane = threadIdx.x & 31;
    const bool is_j = gw >= NROWS;
    const int row = is_j ? gw - NROWS : gw;
    const float* src = is_j ? g_proj_j : g_proj_i;

    const float2 v = *(const float2*)(src + (size_t)row * PDIM + lane * 2);
    float s = v.x + v.y;
    float q = fmaf(v.x, v.x, v.y * v.y);
#pragma unroll
    for (int off = 16; off > 0; off >>= 1) {
        s += __shfl_xor_sync(0xffffffffu, s, off);
        q += __shfl_xor_sync(0xffffffffu, q, off);
    }
    if (lane == 0) {
        const float inv64 = 1.0f / 64.0f;
        float2 o = make_float2(s * inv64, q * inv64);
        if (is_j) g_mt_j[row] = o; else g_mt_i[row] = o;
    }
}

// ---------------------------------------------------------------------------
// Kernel 3: block = (b, 4 i-rows).
// Prologue: dot(a_ii, c_j) for all 4x1024 pairs via transposed proj_j
//           -> {mu, rinv} in smem. Main loop: NO reductions; streaming stores.
// ---------------------------------------------------------------------------
__global__ __launch_bounds__(256) void pair_kernel(
    const float* __restrict__ gamma, const float* __restrict__ beta,
    const float* __restrict__ embed, float* __restrict__ out)
{
    __shared__ __align__(16) float2 s_d[IT][NSEQ];   // {mu, rinv}  32 KB
    __shared__ float s_a[IT][PDIM];                  // 1 KB

    const int i0 = blockIdx.x * IT;
    const int b  = blockIdx.y;
    const int t  = threadIdx.x;

    s_a[t >> 6][t & 63] = g_proj_i[((size_t)(b * NSEQ + i0)) * PDIM + t];
    __syncthreads();

    // ---- prologue: thread t owns 4 consecutive j, all IT i's ----
    {
        const int j0 = t * 4;
        const float* __restrict__ cT = g_proj_jT + (size_t)b * PDIM * NSEQ + j0;
        float acc[IT][4] = {};
#pragma unroll 4
        for (int p = 0; p < PDIM; p++) {
            const float4 c4 = *(const float4*)(cT + (size_t)p * NSEQ);
#pragma unroll
            for (int ii = 0; ii < IT; ii++) {
                const float av = s_a[ii][p];
                acc[ii][0] = fmaf(av, c4.x, acc[ii][0]);
                acc[ii][1] = fmaf(av, c4.y, acc[ii][1]);
                acc[ii][2] = fmaf(av, c4.z, acc[ii][2]);
                acc[ii][3] = fmaf(av, c4.w, acc[ii][3]);
            }
        }
        float2 mti[IT];
#pragma unroll
        for (int ii = 0; ii < IT; ii++) mti[ii] = g_mt_i[b * NSEQ + i0 + ii];

        const float inv32 = 1.0f / 32.0f;
#pragma unroll
        for (int jj = 0; jj < 4; jj++) {
            const float2 mtj = g_mt_j[b * NSEQ + j0 + jj];
#pragma unroll
            for (int ii = 0; ii < IT; ii++) {
                const float mu  = mti[ii].x + mtj.x;
                const float e2  = fmaf(acc[ii][jj], inv32, mti[ii].y + mtj.y);
                const float var = fmaf(-mu, mu, e2);
                s_d[ii][j0 + jj] = make_float2(mu, rsqrtf(var + 1e-5f));
            }
        }
    }

    const int lane = t & 31;
    const int w = t >> 5;
    const int h = lane >> 4;
    const int li = lane & 15;

    const float4 gm   = *(const float4*)(gamma + li * 4);
    const float4 bt   = *(const float4*)(beta + li * 4);
    const float4 e_lo = *(const float4*)(embed + li * 4);
    const float4 e_hi = *(const float4*)(embed + 2 * MAXREL * PDIM + li * 4);

    __syncthreads();   // s_d ready

    float4 a[IT];
#pragma unroll
    for (int ii = 0; ii < IT; ii++)
        a[ii] = *(const float4*)&s_a[ii][li * 4];

    const float* __restrict__ pj = g_proj_j + (size_t)b * NSEQ * PDIM;
    float* obase = out + ((size_t)(b * NSEQ + i0)) * NSEQ * PDIM + li * 4;

#pragma unroll 2
    for (int jb = 0; jb < NSEQ; jb += 16) {
        const int j = jb + w * 2 + h;
        const float4 c = *(const float4*)(pj + (size_t)j * PDIM + li * 4);

#pragma unroll
        for (int ii = 0; ii < IT; ii++) {
            const float2 mr = s_d[ii][j];
            const float mu = mr.x, rinv = mr.y;

            float4 x;
            x.x = a[ii].x + c.x; x.y = a[ii].y + c.y;
            x.z = a[ii].z + c.z; x.w = a[ii].w + c.w;

            const float rgx = rinv * gm.x, rgy = rinv * gm.y;
            const float rgz = rinv * gm.z, rgw = rinv * gm.w;
            const float bx = fmaf(-mu, rgx, bt.x), by = fmaf(-mu, rgy, bt.y);
            const float bz = fmaf(-mu, rgz, bt.z), bw = fmaf(-mu, rgw, bt.w);

            float4 y;
            y.x = fmaxf(fmaf(x.x, rgx, bx), 0.f);
            y.y = fmaxf(fmaf(x.y, rgy, by), 0.f);
            y.z = fmaxf(fmaf(x.z, rgz, bz), 0.f);
            y.w = fmaxf(fmaf(x.w, rgw, bw), 0.f);

            const int dji = j - (i0 + ii);
            float4 e;
            if (dji <= -MAXREL)      e = e_lo;
            else if (dji >= MAXREL)  e = e_hi;
            else e = *(const float4*)(embed + (dji + MAXREL) * PDIM + li * 4);

            y.x += e.x; y.y += e.y; y.z += e.z; y.w += e.w;

            // streaming store: output is never re-read; keep L2 for proj_j
            __stcs((float4*)(obase + (size_t)ii * NSEQ * PDIM + (size_t)j * PDIM), y);
        }
    }
}

extern "C" void kernel_launch(void* const* d_in, const int* in_sizes, int n_in,
                              void* d_out, int out_size)
{
    const float* single = (const float*)d_in[0];
    const float* W      = (const float*)d_in[1];
    const float* bias   = (const float*)d_in[2];
    const float* gamma  = (const float*)d_in[3];
    const float* beta   = (const float*)d_in[4];
    const float* embed  = (const float*)d_in[5];
    float* out = (float*)d_out;

    proj_kernel<<<NROWS / PR, 256>>>(single, W, bias);

    stats_kernel<<<(2 * NROWS) / 8, 256>>>();

    dim3 grid(NSEQ / IT, BATCH);
    pair_kernel<<<grid, 256>>>(gamma, beta, embed, out);
}